// round 9
// baseline (speedup 1.0000x reference)
#include <cuda_runtime.h>
#include <climits>

// Problem shape (fixed): B=4, C=1, D=64, H=256, W=256
#define SLICES      256                 // B*D
#define SPLIT       8                   // parts per slice
#define NBLOCKS     (SLICES * SPLIT)    // 2048
#define THREADS     256
#define PART_F4     2048                // float4 per part
#define ITERS       8                   // stages of 256 float4
#define STAGES      4                   // smem ring depth
#define ROWS_PER_PART 32
#define TOTAL_ELEMS 16777216.0f
#define NBOX_ELEMS  1024.0f
#define LN2F        0.6931471805599453f

// Scratch (no allocation allowed) — partials per block
__device__ float        g_seg[NBLOCKS];
__device__ int4         g_box[NBLOCKS];   // x=minR, y=maxR, z=minC, w=maxC
__device__ unsigned int g_count = 0;

__device__ __forceinline__ void cpa16(void* sdst, const void* gsrc) {
    unsigned sa = (unsigned)__cvta_generic_to_shared(sdst);
    asm volatile("cp.async.cg.shared.global [%0], [%1], 16;" :: "r"(sa), "l"(gsrc) : "memory");
}
__device__ __forceinline__ void cpa_commit() {
    asm volatile("cp.async.commit_group;" ::: "memory");
}
__device__ __forceinline__ void cpa_wait2() {
    asm volatile("cp.async.wait_group 2;" ::: "memory");
}

__global__ void __launch_bounds__(THREADS, 6) fused_kernel(
    const float4* __restrict__ x4p, const float4* __restrict__ t4p,
    const float*  __restrict__ tgt, float* __restrict__ out)
{
    __shared__ __align__(16) float4 s_x[STAGES][THREADS];
    __shared__ __align__(16) float4 s_t[STAGES][THREADS];

    const int blk  = blockIdx.x;            // blk = slice*SPLIT + part
    const int tid  = threadIdx.x;
    const int part = blk & (SPLIT - 1);
    const int rowBase = part * ROWS_PER_PART;

    const float4* __restrict__ xb = x4p + (size_t)blk * PART_F4 + tid;
    const float4* __restrict__ tb = t4p + (size_t)blk * PART_F4 + tid;

    // Accumulators. Columns are FIXED per thread (stride 256 ≡ 0 mod 64).
    float cm0 = -1.0f, cm1 = -1.0f, cm2 = -1.0f, cm3 = -1.0f;
    float aL0 = 0.0f, aL1 = 0.0f;       // Σ (max(x,0) - x·t), two chains
    float accL2 = 0.0f;                 // Σ log2(Π(1+e^-|x|))
    unsigned rmask = 0;                 // bit k: any(x>0) in k-th visited row

    // ---- prologue: stages 0..2 in flight ----
    #pragma unroll
    for (int s = 0; s < STAGES - 1; ++s) {
        cpa16(&s_x[s][tid], xb + s * THREADS);
        cpa16(&s_t[s][tid], tb + s * THREADS);
        cpa_commit();
    }

    // Each thread reads ONLY data it staged itself -> no __syncthreads needed.
    // Group j contains stage j; wait_group 2 at iter k => stage k resident.
    #pragma unroll
    for (int k = 0; k < ITERS; ++k) {
        cpa_wait2();
        const int slot = k & (STAGES - 1);
        const float4 xv = s_x[slot][tid];
        const float4 tv = s_t[slot][tid];

        if (k + STAGES - 1 < ITERS) {
            const int ns = (k + STAGES - 1) & (STAGES - 1);
            cpa16(&s_x[ns][tid], xb + (k + STAGES - 1) * THREADS);
            cpa16(&s_t[ns][tid], tb + (k + STAGES - 1) * THREADS);
        }
        cpa_commit();   // commit every iter (possibly empty) keeps group math uniform

        // one LG2 per 4 elements: log2((1+e0)(1+e1)(1+e2)(1+e3))
        float e0 = __expf(-fabsf(xv.x));
        float e1 = __expf(-fabsf(xv.y));
        float a01 = 1.0f + e0;
        float p01 = __fmaf_rn(e1, a01, a01);       // (1+e0)(1+e1)
        float e2 = __expf(-fabsf(xv.z));
        float e3 = __expf(-fabsf(xv.w));
        float a23 = 1.0f + e2;
        float p23 = __fmaf_rn(e3, a23, a23);       // (1+e2)(1+e3)
        accL2 += __log2f(p01 * p23);

        // linear terms: Σ max(x,0) - x·t, two chains
        aL0 += fmaxf(xv.x, 0.0f);
        aL0  = __fmaf_rn(-xv.x, tv.x, aL0);
        aL1 += fmaxf(xv.y, 0.0f);
        aL1  = __fmaf_rn(-xv.y, tv.y, aL1);
        aL0 += fmaxf(xv.z, 0.0f);
        aL0  = __fmaf_rn(-xv.z, tv.z, aL0);
        aL1 += fmaxf(xv.w, 0.0f);
        aL1  = __fmaf_rn(-xv.w, tv.w, aL1);

        // bbox: per-column running max + per-row any
        cm0 = fmaxf(cm0, xv.x);
        cm1 = fmaxf(cm1, xv.y);
        cm2 = fmaxf(cm2, xv.z);
        cm3 = fmaxf(cm3, xv.w);
        float m4 = fmaxf(fmaxf(xv.x, xv.y), fmaxf(xv.z, xv.w));
        if (m4 > 0.0f) rmask |= (1u << k);
    }

    // Decode per-thread bbox contribution
    int minR, maxR, minC, maxC;
    {
        const int rb = rowBase + (tid >> 6);   // rows visited: rb + 4k
        if (rmask) {
            minR = rb + 4 * (__ffs(rmask) - 1);
            maxR = rb + 4 * (31 - __clz(rmask));
        } else { minR = INT_MAX; maxR = -1; }

        const int cb = (tid & 63) << 2;
        unsigned cmsk = (cm0 > 0.0f ? 1u : 0u) | (cm1 > 0.0f ? 2u : 0u)
                      | (cm2 > 0.0f ? 4u : 0u) | (cm3 > 0.0f ? 8u : 0u);
        if (cmsk) {
            minC = cb + (__ffs(cmsk) - 1);
            maxC = cb + (31 - __clz(cmsk));
        } else { minC = INT_MAX; maxC = -1; }
    }

    float seg = (aL0 + aL1) + LN2F * accL2;

    // ---- intra-warp reduction (shuffle) ----
    #pragma unroll
    for (int off = 16; off > 0; off >>= 1) {
        seg  += __shfl_xor_sync(0xFFFFFFFFu, seg,  off);
        minR  = min(minR, __shfl_xor_sync(0xFFFFFFFFu, minR, off));
        maxR  = max(maxR, __shfl_xor_sync(0xFFFFFFFFu, maxR, off));
        minC  = min(minC, __shfl_xor_sync(0xFFFFFFFFu, minC, off));
        maxC  = max(maxC, __shfl_xor_sync(0xFFFFFFFFu, maxC, off));
    }

    // ---- cross-warp reduction via smem (8 warps) ----
    __shared__ float s_seg[8];
    __shared__ int   s_mnR[8], s_mxR[8], s_mnC[8], s_mxC[8];
    const int wid = tid >> 5, lid = tid & 31;
    if (lid == 0) {
        s_seg[wid] = seg;
        s_mnR[wid] = minR; s_mxR[wid] = maxR;
        s_mnC[wid] = minC; s_mxC[wid] = maxC;
    }
    __syncthreads();
    if (tid == 0) {
        float rs = s_seg[0];
        int rmnR = s_mnR[0], rmxR = s_mxR[0], rmnC = s_mnC[0], rmxC = s_mxC[0];
        #pragma unroll
        for (int w = 1; w < 8; ++w) {
            rs   += s_seg[w];
            rmnR  = min(rmnR, s_mnR[w]); rmxR = max(rmxR, s_mxR[w]);
            rmnC  = min(rmnC, s_mnC[w]); rmxC = max(rmxC, s_mxC[w]);
        }
        g_seg[blk] = rs;
        g_box[blk] = make_int4(rmnR, rmxR, rmnC, rmxC);
    }

    // ---- last-block-finishes tail ----
    __shared__ bool s_isLast;
    __threadfence();
    if (tid == 0) {
        unsigned int c = atomicAdd(&g_count, 1u);
        s_isLast = (c == NBLOCKS - 1);
    }
    __syncthreads();
    if (!s_isLast) return;

    // Tail: thread s handles slice s (256 threads)
    const int s = tid;
    float segT = 0.0f;
    int mnR = INT_MAX, mxR = -1, mnC = INT_MAX, mxC = -1;
    #pragma unroll
    for (int p = 0; p < SPLIT; ++p) {
        int idx = s * SPLIT + p;
        segT += __ldcg(&g_seg[idx]);
        int4 b = __ldcg(&g_box[idx]);
        mnR = min(mnR, b.x); mxR = max(mxR, b.y);
        mnC = min(mnC, b.z); mxC = max(mxC, b.w);
    }

    float bx, by, bw, bh;
    if (mxR < 0) {                       // empty mask
        bx = 0.0f; by = 0.0f; bw = 256.0f; bh = 256.0f;
    } else {
        bx = (float)mnC; by = (float)mnR;
        bw = (float)(mxC - mnC); bh = (float)(mxR - mnR);
    }

    float pred[4] = {bx, by, bw, bh};
    float l = 0.0f;
    #pragma unroll
    for (int j = 0; j < 4; ++j) {
        float d  = pred[j] - tgt[s * 4 + j];
        float ad = fabsf(d);
        l += (ad < 1.0f) ? 0.5f * d * d : ad - 0.5f;
    }

    // reduce 256 lanes: warp shuffle + smem
    #pragma unroll
    for (int off = 16; off > 0; off >>= 1) {
        segT += __shfl_xor_sync(0xFFFFFFFFu, segT, off);
        l    += __shfl_xor_sync(0xFFFFFFFFu, l,    off);
    }
    __shared__ float t_seg[8], t_box[8];
    const int wid2 = tid >> 5, lid2 = tid & 31;
    if (lid2 == 0) { t_seg[wid2] = segT; t_box[wid2] = l; }
    __syncthreads();
    if (tid == 0) {
        float fs = 0.0f, fb = 0.0f;
        #pragma unroll
        for (int w = 0; w < 8; ++w) { fs += t_seg[w]; fb += t_box[w]; }
        out[0] = fs / TOTAL_ELEMS;
        out[1] = fb / NBOX_ELEMS;
        g_count = 0;                     // reset for next graph replay
    }
}

extern "C" void kernel_launch(void* const* d_in, const int* in_sizes, int n_in,
                              void* d_out, int out_size)
{
    const float4* x4 = (const float4*)d_in[0];   // model_output
    const float4* t4 = (const float4*)d_in[1];   // target_masks
    const float*  tb = (const float*)d_in[2];    // target_bboxes
    float* out = (float*)d_out;

    fused_kernel<<<NBLOCKS, THREADS>>>(x4, t4, tb, out);
}

// round 10
// speedup vs baseline: 1.0926x; 1.0926x over previous
#include <cuda_runtime.h>
#include <climits>

// Problem shape (fixed): B=4, C=1, D=64, H=256, W=256
#define SLICES      256                 // B*D
#define SPLIT       2                   // parts per slice
#define NBLOCKS     (SLICES * SPLIT)    // 512  -> single wave
#define THREADS     256
#define PART_F4     8192                // float4 per part (32768 elems)
#define ITERS       32                  // stages of 256 float4
#define STAGES      4                   // smem ring depth
#define ROWS_PER_PART 128
#define TOTAL_ELEMS 16777216.0f
#define NBOX_ELEMS  1024.0f
#define LN2F        0.6931471805599453f

// Scratch (no allocation allowed) — partials per block
__device__ float        g_seg[NBLOCKS];
__device__ int4         g_box[NBLOCKS];   // x=minR, y=maxR, z=minC, w=maxC
__device__ unsigned int g_count = 0;

__device__ __forceinline__ void cpa16(void* sdst, const void* gsrc) {
    unsigned sa = (unsigned)__cvta_generic_to_shared(sdst);
    asm volatile("cp.async.cg.shared.global [%0], [%1], 16;" :: "r"(sa), "l"(gsrc) : "memory");
}
__device__ __forceinline__ void cpa_commit() {
    asm volatile("cp.async.commit_group;" ::: "memory");
}
__device__ __forceinline__ void cpa_wait2() {
    asm volatile("cp.async.wait_group 2;" ::: "memory");
}

__global__ void __launch_bounds__(THREADS) fused_kernel(
    const float4* __restrict__ x4p, const float4* __restrict__ t4p,
    const float*  __restrict__ tgt, float* __restrict__ out)
{
    __shared__ __align__(16) float4 s_x[STAGES][THREADS];
    __shared__ __align__(16) float4 s_t[STAGES][THREADS];

    const int blk  = blockIdx.x;            // blk = slice*SPLIT + part
    const int tid  = threadIdx.x;
    const int part = blk & (SPLIT - 1);
    const int rowBase = part * ROWS_PER_PART;

    const float4* __restrict__ xb = x4p + (size_t)blk * PART_F4 + tid;
    const float4* __restrict__ tb = t4p + (size_t)blk * PART_F4 + tid;

    // Accumulators. Columns are FIXED per thread (stride 256 ≡ 0 mod 64).
    float cm0 = -1.0f, cm1 = -1.0f, cm2 = -1.0f, cm3 = -1.0f;
    float aL0 = 0.0f, aL1 = 0.0f;       // Σ (max(x,0) - x·t), two chains
    float accL2 = 0.0f;                 // Σ log2(Π(1+e^-|x|))
    unsigned rmask = 0;                 // bit k: any(x>0) in k-th visited row (32 rows)

    // ---- prologue: stages 0..2 in flight ----
    #pragma unroll
    for (int s = 0; s < STAGES - 1; ++s) {
        cpa16(&s_x[s][tid], xb + s * THREADS);
        cpa16(&s_t[s][tid], tb + s * THREADS);
        cpa_commit();
    }

    // Each thread reads ONLY data it staged itself -> no __syncthreads needed.
    // Group j contains stage j; wait_group 2 at iter k => stage k resident.
    #pragma unroll 4
    for (int k = 0; k < ITERS; ++k) {
        cpa_wait2();
        const int slot = k & (STAGES - 1);
        const float4 xv = s_x[slot][tid];
        const float4 tv = s_t[slot][tid];

        if (k + STAGES - 1 < ITERS) {
            const int ns = (k + STAGES - 1) & (STAGES - 1);
            cpa16(&s_x[ns][tid], xb + (k + STAGES - 1) * THREADS);
            cpa16(&s_t[ns][tid], tb + (k + STAGES - 1) * THREADS);
        }
        cpa_commit();   // commit every iter (possibly empty) keeps group math uniform

        // one LG2 per 4 elements: log2((1+e0)(1+e1)(1+e2)(1+e3))
        float e0 = __expf(-fabsf(xv.x));
        float e1 = __expf(-fabsf(xv.y));
        float a01 = 1.0f + e0;
        float p01 = __fmaf_rn(e1, a01, a01);       // (1+e0)(1+e1)
        float e2 = __expf(-fabsf(xv.z));
        float e3 = __expf(-fabsf(xv.w));
        float a23 = 1.0f + e2;
        float p23 = __fmaf_rn(e3, a23, a23);       // (1+e2)(1+e3)
        accL2 += __log2f(p01 * p23);

        // linear terms: Σ max(x,0) - x·t, two chains
        aL0 += fmaxf(xv.x, 0.0f);
        aL0  = __fmaf_rn(-xv.x, tv.x, aL0);
        aL1 += fmaxf(xv.y, 0.0f);
        aL1  = __fmaf_rn(-xv.y, tv.y, aL1);
        aL0 += fmaxf(xv.z, 0.0f);
        aL0  = __fmaf_rn(-xv.z, tv.z, aL0);
        aL1 += fmaxf(xv.w, 0.0f);
        aL1  = __fmaf_rn(-xv.w, tv.w, aL1);

        // bbox: per-column running max + per-row any
        cm0 = fmaxf(cm0, xv.x);
        cm1 = fmaxf(cm1, xv.y);
        cm2 = fmaxf(cm2, xv.z);
        cm3 = fmaxf(cm3, xv.w);
        float m4 = fmaxf(fmaxf(xv.x, xv.y), fmaxf(xv.z, xv.w));
        if (m4 > 0.0f) rmask |= (1u << k);
    }

    // Decode per-thread bbox contribution
    int minR, maxR, minC, maxC;
    {
        const int rb = rowBase + (tid >> 6);   // rows visited: rb + 4k, k=0..31
        if (rmask) {
            minR = rb + 4 * (__ffs(rmask) - 1);
            maxR = rb + 4 * (31 - __clz(rmask));
        } else { minR = INT_MAX; maxR = -1; }

        const int cb = (tid & 63) << 2;
        unsigned cmsk = (cm0 > 0.0f ? 1u : 0u) | (cm1 > 0.0f ? 2u : 0u)
                      | (cm2 > 0.0f ? 4u : 0u) | (cm3 > 0.0f ? 8u : 0u);
        if (cmsk) {
            minC = cb + (__ffs(cmsk) - 1);
            maxC = cb + (31 - __clz(cmsk));
        } else { minC = INT_MAX; maxC = -1; }
    }

    float seg = (aL0 + aL1) + LN2F * accL2;

    // ---- intra-warp reduction (shuffle) ----
    #pragma unroll
    for (int off = 16; off > 0; off >>= 1) {
        seg  += __shfl_xor_sync(0xFFFFFFFFu, seg,  off);
        minR  = min(minR, __shfl_xor_sync(0xFFFFFFFFu, minR, off));
        maxR  = max(maxR, __shfl_xor_sync(0xFFFFFFFFu, maxR, off));
        minC  = min(minC, __shfl_xor_sync(0xFFFFFFFFu, minC, off));
        maxC  = max(maxC, __shfl_xor_sync(0xFFFFFFFFu, maxC, off));
    }

    // ---- cross-warp reduction via smem (8 warps) ----
    __shared__ float s_seg[8];
    __shared__ int   s_mnR[8], s_mxR[8], s_mnC[8], s_mxC[8];
    const int wid = tid >> 5, lid = tid & 31;
    if (lid == 0) {
        s_seg[wid] = seg;
        s_mnR[wid] = minR; s_mxR[wid] = maxR;
        s_mnC[wid] = minC; s_mxC[wid] = maxC;
    }
    __syncthreads();
    if (tid == 0) {
        float rs = s_seg[0];
        int rmnR = s_mnR[0], rmxR = s_mxR[0], rmnC = s_mnC[0], rmxC = s_mxC[0];
        #pragma unroll
        for (int w = 1; w < 8; ++w) {
            rs   += s_seg[w];
            rmnR  = min(rmnR, s_mnR[w]); rmxR = max(rmxR, s_mxR[w]);
            rmnC  = min(rmnC, s_mnC[w]); rmxC = max(rmxC, s_mxC[w]);
        }
        g_seg[blk] = rs;
        g_box[blk] = make_int4(rmnR, rmxR, rmnC, rmxC);
    }

    // ---- last-block-finishes tail ----
    __shared__ bool s_isLast;
    __threadfence();
    if (tid == 0) {
        unsigned int c = atomicAdd(&g_count, 1u);
        s_isLast = (c == NBLOCKS - 1);
    }
    __syncthreads();
    if (!s_isLast) return;

    // Tail: thread s handles slice s (256 threads)
    const int s = tid;
    float segT = 0.0f;
    int mnR = INT_MAX, mxR = -1, mnC = INT_MAX, mxC = -1;
    #pragma unroll
    for (int p = 0; p < SPLIT; ++p) {
        int idx = s * SPLIT + p;
        segT += __ldcg(&g_seg[idx]);
        int4 b = __ldcg(&g_box[idx]);
        mnR = min(mnR, b.x); mxR = max(mxR, b.y);
        mnC = min(mnC, b.z); mxC = max(mxC, b.w);
    }

    float bx, by, bw, bh;
    if (mxR < 0) {                       // empty mask
        bx = 0.0f; by = 0.0f; bw = 256.0f; bh = 256.0f;
    } else {
        bx = (float)mnC; by = (float)mnR;
        bw = (float)(mxC - mnC); bh = (float)(mxR - mnR);
    }

    float pred[4] = {bx, by, bw, bh};
    float l = 0.0f;
    #pragma unroll
    for (int j = 0; j < 4; ++j) {
        float d  = pred[j] - tgt[s * 4 + j];
        float ad = fabsf(d);
        l += (ad < 1.0f) ? 0.5f * d * d : ad - 0.5f;
    }

    // reduce 256 lanes: warp shuffle + smem
    #pragma unroll
    for (int off = 16; off > 0; off >>= 1) {
        segT += __shfl_xor_sync(0xFFFFFFFFu, segT, off);
        l    += __shfl_xor_sync(0xFFFFFFFFu, l,    off);
    }
    __shared__ float t_seg[8], t_box[8];
    const int wid2 = tid >> 5, lid2 = tid & 31;
    if (lid2 == 0) { t_seg[wid2] = segT; t_box[wid2] = l; }
    __syncthreads();
    if (tid == 0) {
        float fs = 0.0f, fb = 0.0f;
        #pragma unroll
        for (int w = 0; w < 8; ++w) { fs += t_seg[w]; fb += t_box[w]; }
        out[0] = fs / TOTAL_ELEMS;
        out[1] = fb / NBOX_ELEMS;
        g_count = 0;                     // reset for next graph replay
    }
}

extern "C" void kernel_launch(void* const* d_in, const int* in_sizes, int n_in,
                              void* d_out, int out_size)
{
    const float4* x4 = (const float4*)d_in[0];   // model_output
    const float4* t4 = (const float4*)d_in[1];   // target_masks
    const float*  tb = (const float*)d_in[2];    // target_bboxes
    float* out = (float*)d_out;

    fused_kernel<<<NBLOCKS, THREADS>>>(x4, t4, tb, out);
}

// round 11
// speedup vs baseline: 1.0962x; 1.0033x over previous
#include <cuda_runtime.h>
#include <climits>

// Problem shape (fixed): B=4, C=1, D=64, H=256, W=256
#define SLICES      256                 // B*D
#define SPLIT       2                   // parts per slice
#define NBLOCKS     (SLICES * SPLIT)    // 512  -> single wave
#define THREADS     256
#define PART_F4     8192                // float4 per part (128KB x + 128KB t)
#define STAGE_F4    512                 // float4 per stage per stream (8KB)
#define STAGE_BYTES 8192
#define NSTAGES     16                  // PART_F4 / STAGE_F4
#define RING        2                   // double buffer
#define ROWS_PER_PART 128
#define TOTAL_ELEMS 16777216.0f
#define NBOX_ELEMS  1024.0f
#define LN2F        0.6931471805599453f

// Scratch (no allocation allowed) — partials per block
__device__ float        g_seg[NBLOCKS];
__device__ int4         g_box[NBLOCKS];   // x=minR, y=maxR, z=minC, w=maxC
__device__ unsigned int g_count = 0;

__device__ __forceinline__ unsigned s2u(const void* p) {
    return (unsigned)__cvta_generic_to_shared(p);
}
__device__ __forceinline__ void mb_init(void* p, unsigned cnt) {
    asm volatile("mbarrier.init.shared.b64 [%0], %1;" :: "r"(s2u(p)), "r"(cnt) : "memory");
}
__device__ __forceinline__ void mb_expect_tx(void* p, unsigned bytes) {
    asm volatile("mbarrier.arrive.expect_tx.shared.b64 _, [%0], %1;"
                 :: "r"(s2u(p)), "r"(bytes) : "memory");
}
__device__ __forceinline__ void mb_arrive(void* p) {
    asm volatile("mbarrier.arrive.shared.b64 _, [%0];" :: "r"(s2u(p)) : "memory");
}
__device__ __forceinline__ void mb_wait(void* p, unsigned parity) {
    asm volatile(
        "{\n\t.reg .pred P;\n"
        "WL_%=:\n\t"
        "mbarrier.try_wait.parity.acquire.cta.shared::cta.b64 P, [%0], %1, 0x989680;\n\t"
        "@P bra WD_%=;\n\t"
        "bra WL_%=;\n"
        "WD_%=:\n\t}"
        :: "r"(s2u(p)), "r"(parity) : "memory");
}
__device__ __forceinline__ void bulk_cp(void* sdst, const void* gsrc, unsigned bytes, void* mbar) {
    asm volatile(
        "cp.async.bulk.shared::cta.global.mbarrier::complete_tx::bytes [%0], [%1], %2, [%3];"
        :: "r"(s2u(sdst)), "l"(gsrc), "r"(bytes), "r"(s2u(mbar)) : "memory");
}

__global__ void __launch_bounds__(THREADS) fused_kernel(
    const float4* __restrict__ x4p, const float4* __restrict__ t4p,
    const float*  __restrict__ tgt, float* __restrict__ out)
{
    __shared__ __align__(16) float4 s_x[RING][STAGE_F4];
    __shared__ __align__(16) float4 s_t[RING][STAGE_F4];
    __shared__ __align__(8)  unsigned long long mb_full[RING], mb_empty[RING];

    const int blk  = blockIdx.x;            // blk = slice*SPLIT + part
    const int tid  = threadIdx.x;
    const int part = blk & (SPLIT - 1);
    const int rowBase = part * ROWS_PER_PART;

    const float4* __restrict__ xg = x4p + (size_t)blk * PART_F4;
    const float4* __restrict__ tg = t4p + (size_t)blk * PART_F4;

    // Accumulators. Columns are FIXED per thread ((tid&63) ≡ col group).
    float cm0 = -1.0f, cm1 = -1.0f, cm2 = -1.0f, cm3 = -1.0f;
    float aL0 = 0.0f, aL1 = 0.0f;       // Σ (max(x,0) - x·t), two chains
    float accL2 = 0.0f;                 // Σ log2(Π(1+e^-|x|))
    unsigned rmask = 0;                 // bit b=2s+j: any(x>0) at row rb + 4b

    if (tid == 0) {
        mb_init(&mb_full[0], 1);  mb_init(&mb_full[1], 1);
        mb_init(&mb_empty[0], THREADS); mb_init(&mb_empty[1], THREADS);
    }
    __syncthreads();
    asm volatile("fence.proxy.async.shared::cta;" ::: "memory");

    // ---- prologue: issue stages 0,1 ----
    if (tid == 0) {
        #pragma unroll
        for (int s = 0; s < RING; ++s) {
            mb_expect_tx(&mb_full[s], 2 * STAGE_BYTES);
            bulk_cp(&s_x[s][0], xg + s * STAGE_F4, STAGE_BYTES, &mb_full[s]);
            bulk_cp(&s_t[s][0], tg + s * STAGE_F4, STAGE_BYTES, &mb_full[s]);
        }
    }

    #pragma unroll 2
    for (int s = 0; s < NSTAGES; ++s) {
        const int slot = s & 1;
        const unsigned u = (unsigned)(s >> 1);
        mb_wait(&mb_full[slot], u & 1u);

        #pragma unroll
        for (int j = 0; j < 2; ++j) {
            const float4 xv = s_x[slot][tid + THREADS * j];
            const float4 tv = s_t[slot][tid + THREADS * j];

            // one LG2 per 4 elements: log2((1+e0)(1+e1)(1+e2)(1+e3))
            float e0 = __expf(-fabsf(xv.x));
            float e1 = __expf(-fabsf(xv.y));
            float a01 = 1.0f + e0;
            float p01 = __fmaf_rn(e1, a01, a01);
            float e2 = __expf(-fabsf(xv.z));
            float e3 = __expf(-fabsf(xv.w));
            float a23 = 1.0f + e2;
            float p23 = __fmaf_rn(e3, a23, a23);
            accL2 += __log2f(p01 * p23);

            // linear terms: Σ max(x,0) - x·t, two chains
            aL0 += fmaxf(xv.x, 0.0f);
            aL0  = __fmaf_rn(-xv.x, tv.x, aL0);
            aL1 += fmaxf(xv.y, 0.0f);
            aL1  = __fmaf_rn(-xv.y, tv.y, aL1);
            aL0 += fmaxf(xv.z, 0.0f);
            aL0  = __fmaf_rn(-xv.z, tv.z, aL0);
            aL1 += fmaxf(xv.w, 0.0f);
            aL1  = __fmaf_rn(-xv.w, tv.w, aL1);

            // bbox: per-column running max + per-row any
            cm0 = fmaxf(cm0, xv.x);
            cm1 = fmaxf(cm1, xv.y);
            cm2 = fmaxf(cm2, xv.z);
            cm3 = fmaxf(cm3, xv.w);
            float m4 = fmaxf(fmaxf(xv.x, xv.y), fmaxf(xv.z, xv.w));
            if (m4 > 0.0f) rmask |= (1u << (2 * s + j));
        }

        mb_arrive(&mb_empty[slot]);

        if (tid == 0 && s + RING < NSTAGES) {
            mb_wait(&mb_empty[slot], u & 1u);     // all 256 consumed this slot
            mb_expect_tx(&mb_full[slot], 2 * STAGE_BYTES);
            bulk_cp(&s_x[slot][0], xg + (s + RING) * STAGE_F4, STAGE_BYTES, &mb_full[slot]);
            bulk_cp(&s_t[slot][0], tg + (s + RING) * STAGE_F4, STAGE_BYTES, &mb_full[slot]);
        }
    }

    // Decode per-thread bbox contribution
    int minR, maxR, minC, maxC;
    {
        const int rb = rowBase + (tid >> 6);   // rows visited: rb + 4b, b=0..31
        if (rmask) {
            minR = rb + 4 * (__ffs(rmask) - 1);
            maxR = rb + 4 * (31 - __clz(rmask));
        } else { minR = INT_MAX; maxR = -1; }

        const int cb = (tid & 63) << 2;
        unsigned cmsk = (cm0 > 0.0f ? 1u : 0u) | (cm1 > 0.0f ? 2u : 0u)
                      | (cm2 > 0.0f ? 4u : 0u) | (cm3 > 0.0f ? 8u : 0u);
        if (cmsk) {
            minC = cb + (__ffs(cmsk) - 1);
            maxC = cb + (31 - __clz(cmsk));
        } else { minC = INT_MAX; maxC = -1; }
    }

    float seg = (aL0 + aL1) + LN2F * accL2;

    // ---- intra-warp reduction (shuffle) ----
    #pragma unroll
    for (int off = 16; off > 0; off >>= 1) {
        seg  += __shfl_xor_sync(0xFFFFFFFFu, seg,  off);
        minR  = min(minR, __shfl_xor_sync(0xFFFFFFFFu, minR, off));
        maxR  = max(maxR, __shfl_xor_sync(0xFFFFFFFFu, maxR, off));
        minC  = min(minC, __shfl_xor_sync(0xFFFFFFFFu, minC, off));
        maxC  = max(maxC, __shfl_xor_sync(0xFFFFFFFFu, maxC, off));
    }

    // ---- cross-warp reduction via smem (8 warps) ----
    __shared__ float s_seg[8];
    __shared__ int   s_mnR[8], s_mxR[8], s_mnC[8], s_mxC[8];
    const int wid = tid >> 5, lid = tid & 31;
    if (lid == 0) {
        s_seg[wid] = seg;
        s_mnR[wid] = minR; s_mxR[wid] = maxR;
        s_mnC[wid] = minC; s_mxC[wid] = maxC;
    }
    __syncthreads();
    if (tid == 0) {
        float rs = s_seg[0];
        int rmnR = s_mnR[0], rmxR = s_mxR[0], rmnC = s_mnC[0], rmxC = s_mxC[0];
        #pragma unroll
        for (int w = 1; w < 8; ++w) {
            rs   += s_seg[w];
            rmnR  = min(rmnR, s_mnR[w]); rmxR = max(rmxR, s_mxR[w]);
            rmnC  = min(rmnC, s_mnC[w]); rmxC = max(rmxC, s_mxC[w]);
        }
        g_seg[blk] = rs;
        g_box[blk] = make_int4(rmnR, rmxR, rmnC, rmxC);
    }

    // ---- last-block-finishes tail ----
    __shared__ bool s_isLast;
    __threadfence();
    if (tid == 0) {
        unsigned int c = atomicAdd(&g_count, 1u);
        s_isLast = (c == NBLOCKS - 1);
    }
    __syncthreads();
    if (!s_isLast) return;

    // Tail: thread s handles slice s (256 threads)
    const int sl = tid;
    float segT = 0.0f;
    int mnR = INT_MAX, mxR = -1, mnC = INT_MAX, mxC = -1;
    #pragma unroll
    for (int p = 0; p < SPLIT; ++p) {
        int idx = sl * SPLIT + p;
        segT += __ldcg(&g_seg[idx]);
        int4 b = __ldcg(&g_box[idx]);
        mnR = min(mnR, b.x); mxR = max(mxR, b.y);
        mnC = min(mnC, b.z); mxC = max(mxC, b.w);
    }

    float bx, by, bw, bh;
    if (mxR < 0) {                       // empty mask
        bx = 0.0f; by = 0.0f; bw = 256.0f; bh = 256.0f;
    } else {
        bx = (float)mnC; by = (float)mnR;
        bw = (float)(mxC - mnC); bh = (float)(mxR - mnR);
    }

    float pred[4] = {bx, by, bw, bh};
    float l = 0.0f;
    #pragma unroll
    for (int j = 0; j < 4; ++j) {
        float d  = pred[j] - tgt[sl * 4 + j];
        float ad = fabsf(d);
        l += (ad < 1.0f) ? 0.5f * d * d : ad - 0.5f;
    }

    // reduce 256 lanes: warp shuffle + smem
    #pragma unroll
    for (int off = 16; off > 0; off >>= 1) {
        segT += __shfl_xor_sync(0xFFFFFFFFu, segT, off);
        l    += __shfl_xor_sync(0xFFFFFFFFu, l,    off);
    }
    __shared__ float t_seg[8], t_box[8];
    const int wid2 = tid >> 5, lid2 = tid & 31;
    if (lid2 == 0) { t_seg[wid2] = segT; t_box[wid2] = l; }
    __syncthreads();
    if (tid == 0) {
        float fs = 0.0f, fb = 0.0f;
        #pragma unroll
        for (int w = 0; w < 8; ++w) { fs += t_seg[w]; fb += t_box[w]; }
        out[0] = fs / TOTAL_ELEMS;
        out[1] = fb / NBOX_ELEMS;
        g_count = 0;                     // reset for next graph replay
    }
}

extern "C" void kernel_launch(void* const* d_in, const int* in_sizes, int n_in,
                              void* d_out, int out_size)
{
    const float4* x4 = (const float4*)d_in[0];   // model_output
    const float4* t4 = (const float4*)d_in[1];   // target_masks
    const float*  tb = (const float*)d_in[2];    // target_bboxes
    float* out = (float*)d_out;

    fused_kernel<<<NBLOCKS, THREADS>>>(x4, t4, tb, out);
}